// round 6
// baseline (speedup 1.0000x reference)
#include <cuda_runtime.h>

#define BB 64
#define TT 512
#define II 512
#define HH 1024
#define NCTA_DIR 64   // CTAs per direction; 128 total <= 148 SMs -> all co-resident

// ---------------- scratch (device globals; no allocations allowed) ----------
__device__ float g_Xrz[2][TT][BB][2 * HH]; // x@W_xr|x@W_xz (+bias), combined cols
__device__ float g_Xh [2][TT][BB][HH];     // x@W_xh (+bias)
__device__ float g_h  [2][BB][HH];         // current hidden state per direction
__device__ float g_RH [2][BB][HH];         // R * h   (phase1 -> phase2)
__device__ float g_Z  [2][BB][HH];         // Z gate  (phase1 -> phase2)
__device__ unsigned g_bar_count[2];
__device__ unsigned g_bar_gen[2];

// ---------------- cp.async helpers -----------------------------------------
__device__ __forceinline__ void cp16(void* smem_dst, const void* gmem_src) {
    unsigned s = (unsigned)__cvta_generic_to_shared(smem_dst);
    asm volatile("cp.async.cg.shared.global [%0], [%1], 16;" :: "r"(s), "l"(gmem_src));
}
#define CP_COMMIT() asm volatile("cp.async.commit_group;")
#define CP_WAIT0()  asm volatile("cp.async.wait_group 0;")

// ------------- per-direction software grid barrier (generation-based) -------
__device__ __forceinline__ void dir_barrier(int dir) {
    __syncthreads();
    if (threadIdx.x == 0) {
        volatile unsigned* vgen = (volatile unsigned*)&g_bar_gen[dir];
        unsigned my = *vgen;
        __threadfence();
        unsigned a = atomicAdd(&g_bar_count[dir], 1u);
        if (a == NCTA_DIR - 1) {
            g_bar_count[dir] = 0;
            __threadfence();
            atomicAdd(&g_bar_gen[dir], 1u);
        } else {
            while (*vgen == my) { }
            __threadfence();
        }
    }
    __syncthreads();
}

// ---------------- input projection: 6x GEMM (32768x512)@(512x1024)+bias -----
// CTA: 256 threads -> 128x64 tile, 32 outputs/thread (8 rows x 4 cols)
__global__ void __launch_bounds__(256) inproj_kernel(
    const float* __restrict__ x,
    const float* __restrict__ Wr_f, const float* __restrict__ br_f,
    const float* __restrict__ Wz_f, const float* __restrict__ bz_f,
    const float* __restrict__ Wh_f, const float* __restrict__ bh_f,
    const float* __restrict__ Wr_b, const float* __restrict__ br_b,
    const float* __restrict__ Wz_b, const float* __restrict__ bz_b,
    const float* __restrict__ Wh_b, const float* __restrict__ bh_b)
{
    const int mat  = blockIdx.z;   // 0..5 : dir*3 + gate
    const int dir  = mat / 3;
    const int gate = mat % 3;      // 0=r, 1=z, 2=h
    const float* W; const float* bias;
    switch (mat) {
        case 0: W = Wr_f; bias = br_f; break;
        case 1: W = Wz_f; bias = bz_f; break;
        case 2: W = Wh_f; bias = bh_f; break;
        case 3: W = Wr_b; bias = br_b; break;
        case 4: W = Wz_b; bias = bz_b; break;
        default: W = Wh_b; bias = bh_b; break;
    }

    const int mTile = blockIdx.x;             // 256 row tiles of 128
    const int cTile = blockIdx.y;             // 16 col tiles of 64
    const int w     = threadIdx.x >> 5;       // warp 0..7
    const int lane  = threadIdx.x & 31;
    const int hf    = lane >> 4;              // half-warp
    const int rbase = w * 16 + hf * 8;        // 8 rows per thread
    const int jc    = cTile * 64 + (lane & 15) * 4;  // 4 cols per thread

    __shared__ float xs[128][64];
    float acc[8][4];
    #pragma unroll
    for (int r = 0; r < 8; ++r)
        #pragma unroll
        for (int c = 0; c < 4; ++c) acc[r][c] = 0.f;

    const float* xbase = x + (size_t)(mTile * 128) * II;

    #pragma unroll 1
    for (int kb = 0; kb < II; kb += 64) {
        // stage 128x64 x-tile
        #pragma unroll
        for (int u = 0; u < 8; ++u) {
            int e  = threadIdx.x + 256 * u;     // 0..2047
            int r  = e >> 4;
            int c4 = (e & 15) * 4;
            *(float4*)&xs[r][c4] = *(const float4*)(xbase + r * II + kb + c4);
        }
        __syncthreads();
        #pragma unroll
        for (int k4 = 0; k4 < 16; ++k4) {
            const int k = kb + 4 * k4;
            const float4 w0 = *(const float4*)&W[(k + 0) * HH + jc];
            const float4 w1 = *(const float4*)&W[(k + 1) * HH + jc];
            const float4 w2 = *(const float4*)&W[(k + 2) * HH + jc];
            const float4 w3 = *(const float4*)&W[(k + 3) * HH + jc];
            #pragma unroll
            for (int r = 0; r < 8; ++r) {
                float4 xv = *(const float4*)&xs[rbase + r][4 * k4];
                acc[r][0] = fmaf(xv.x, w0.x, acc[r][0]);
                acc[r][1] = fmaf(xv.x, w0.y, acc[r][1]);
                acc[r][2] = fmaf(xv.x, w0.z, acc[r][2]);
                acc[r][3] = fmaf(xv.x, w0.w, acc[r][3]);
                acc[r][0] = fmaf(xv.y, w1.x, acc[r][0]);
                acc[r][1] = fmaf(xv.y, w1.y, acc[r][1]);
                acc[r][2] = fmaf(xv.y, w1.z, acc[r][2]);
                acc[r][3] = fmaf(xv.y, w1.w, acc[r][3]);
                acc[r][0] = fmaf(xv.z, w2.x, acc[r][0]);
                acc[r][1] = fmaf(xv.z, w2.y, acc[r][1]);
                acc[r][2] = fmaf(xv.z, w2.z, acc[r][2]);
                acc[r][3] = fmaf(xv.z, w2.w, acc[r][3]);
                acc[r][0] = fmaf(xv.w, w3.x, acc[r][0]);
                acc[r][1] = fmaf(xv.w, w3.y, acc[r][1]);
                acc[r][2] = fmaf(xv.w, w3.z, acc[r][2]);
                acc[r][3] = fmaf(xv.w, w3.w, acc[r][3]);
            }
        }
        __syncthreads();
    }

    const float4 bv = *(const float4*)&bias[jc];
    #pragma unroll
    for (int r = 0; r < 8; ++r) {
        int row = mTile * 128 + rbase + r;   // row = b*T + t
        int b   = row >> 9;                  // /512
        int t   = row & (TT - 1);
        float4 v;
        v.x = acc[r][0] + bv.x;
        v.y = acc[r][1] + bv.y;
        v.z = acc[r][2] + bv.z;
        v.w = acc[r][3] + bv.w;
        if (gate == 0)      *(float4*)&g_Xrz[dir][t][b][jc]      = v;
        else if (gate == 1) *(float4*)&g_Xrz[dir][t][b][HH + jc] = v;
        else                *(float4*)&g_Xh [dir][t][b][jc]      = v;
    }
}

// ---------------- persistent bidirectional GRU recurrence -------------------
// 128 CTAs x 256 threads, 1 CTA/SM. Recurrent weights SMEM-resident (192KB);
// h/RH staging tiles double-buffered via cp.async (FULL 64x64 coverage: 4
// 16B chunks per thread per kb) so the L2 latency of the tile fetch hides
// under the FMA work of the previous block.
// Dynamic smem (floats):
//   Wrz4 [32768]   : phase1 weights [(k>>2)*128 + col*4 + (k&3)]
//   Wh24 [16384]   : phase2 weights [(k>>2)*64  + col*4 + (k&3)]
//   ts [2][64][64] : double-buffered staging tile
#define SM_WH2 32768
#define SM_TS  49152
#define SM_FLOATS (49152 + 2 * 64 * 64)

__global__ void __launch_bounds__(256) gru_rec_kernel(
    const float* __restrict__ hf0, const float* __restrict__ hb0,
    const float* __restrict__ Whr_f, const float* __restrict__ Whz_f, const float* __restrict__ Whh_f,
    const float* __restrict__ Whr_b, const float* __restrict__ Whz_b, const float* __restrict__ Whh_b,
    float* __restrict__ out)
{
    extern __shared__ float sm[];
    float* Wrz4 = sm;
    float* Wh24 = sm + SM_WH2;
    float (*ts)[64][64] = (float(*)[64][64])(sm + SM_TS);

    const int dir = blockIdx.x >> 6;
    const int c   = blockIdx.x & 63;

    const float* __restrict__ Whr = dir ? Whr_b : Whr_f;
    const float* __restrict__ Whz = dir ? Whz_b : Whz_f;
    const float* __restrict__ Whh = dir ? Whh_b : Whh_f;
    const float* __restrict__ h0  = dir ? hb0   : hf0;

    float* __restrict__ hstate = &g_h [dir][0][0];
    float* __restrict__ RH     = &g_RH[dir][0][0];
    float* __restrict__ Zb     = &g_Z [dir][0][0];

    // phase1 geometry: 32 combined cols/CTA over 2048; 8 rows/thread
    const int lane1 = threadIdx.x & 31;
    const int rg1   = (threadIdx.x >> 5) * 8;
    const int jj    = c * 32 + lane1;            // 0..2047 combined [R|Z]
    const float* __restrict__ Wg = (jj < HH) ? Whr : Whz;
    const int jw    = jj & (HH - 1);

    // phase2 geometry: 16 cols/CTA over 1024; 4 rows/thread
    const int lane2 = threadIdx.x & 15;
    const int rg2   = (threadIdx.x >> 4) * 4;
    const int j2    = c * 16 + lane2;

    // staging geometry: FOUR 16B cp.async per thread per kb (full 64x64 tile)
    int srow[4], scol[4];
    #pragma unroll
    for (int u = 0; u < 4; ++u) {
        int e = threadIdx.x + 256 * u;   // 0..1023
        srow[u] = e >> 4;                // 0..63
        scol[u] = (e & 15) * 4;          // 0..60
    }

    // ---- one-time: cache this CTA's weight columns into SMEM ----
    {
        const int wp = threadIdx.x >> 5;
        for (int k = wp; k < HH; k += 8)                 // phase1: col = jj
            Wrz4[(k >> 2) * 128 + lane1 * 4 + (k & 3)] = Wg[k * HH + jw];
        const int wp2 = threadIdx.x >> 4;
        for (int k = wp2; k < HH; k += 16)               // phase2: col = j2
            Wh24[(k >> 2) * 64 + lane2 * 4 + (k & 3)] = Whh[k * HH + j2];
    }

    // init hidden state from h_prev (re-done every replay: deterministic)
    {
        int base = c * 1024;
        #pragma unroll
        for (int u = 0; u < 4; ++u)
            hstate[base + u * 256 + threadIdx.x] = h0[base + u * 256 + threadIdx.x];
    }
    dir_barrier(dir);

    for (int step = 0; step < TT; ++step) {
        const int t = dir ? (TT - 1 - step) : step;

        // ------------------ phase 1: [R|Z] = sigmoid(h@W + x) -------------
        const float* __restrict__ xrz = &g_Xrz[dir][t][0][0];

        // kick off staging of kb=0 immediately
        #pragma unroll
        for (int u = 0; u < 4; ++u)
            cp16(&ts[0][srow[u]][scol[u]], &hstate[srow[u] * HH + scol[u]]);
        CP_COMMIT();

        float xpre[8], hold1[8];
        #pragma unroll
        for (int r = 0; r < 8; ++r) {              // prefetch epilogue operands
            xpre[r]  = __ldg(&xrz[(rg1 + r) * (2 * HH) + jj]);
            hold1[r] = hstate[(rg1 + r) * HH + jw];
        }
        CP_WAIT0();
        __syncthreads();

        float acc[8] = {0.f,0.f,0.f,0.f,0.f,0.f,0.f,0.f};
        #pragma unroll 1
        for (int i = 0; i < 16; ++i) {
            if (i < 15) {
                const int kn = (i + 1) * 64;
                #pragma unroll
                for (int u = 0; u < 4; ++u)
                    cp16(&ts[(i + 1) & 1][srow[u]][scol[u]],
                         &hstate[srow[u] * HH + kn + scol[u]]);
                CP_COMMIT();
            }
            const float (*tb)[64] = ts[i & 1];
            #pragma unroll
            for (int k4 = 0; k4 < 16; ++k4) {
                const int q = i * 16 + k4;
                float4 wv = *(const float4*)&Wrz4[q * 128 + lane1 * 4];
                #pragma unroll
                for (int r = 0; r < 8; ++r) {
                    float4 hv = *(const float4*)&tb[rg1 + r][4 * k4];
                    acc[r] = fmaf(hv.x, wv.x, acc[r]);
                    acc[r] = fmaf(hv.y, wv.y, acc[r]);
                    acc[r] = fmaf(hv.z, wv.z, acc[r]);
                    acc[r] = fmaf(hv.w, wv.w, acc[r]);
                }
            }
            if (i < 15) CP_WAIT0();
            __syncthreads();
        }
        #pragma unroll
        for (int r = 0; r < 8; ++r) {
            const int b = rg1 + r;
            float pre = acc[r] + xpre[r];
            float s   = 1.f / (1.f + __expf(-pre));
            if (jj < HH) RH[b * HH + jw] = s * hold1[r];
            else         Zb[b * HH + jw] = s;
        }
        dir_barrier(dir);

        // ------------------ phase 2: h = Z*tanh(RH@Whh + xh) + (1-Z)*h ----
        const float* __restrict__ xh = &g_Xh[dir][t][0][0];

        #pragma unroll
        for (int u = 0; u < 4; ++u)
            cp16(&ts[0][srow[u]][scol[u]], &RH[srow[u] * HH + scol[u]]);
        CP_COMMIT();

        float xp2[4], zv[4], hv2[4];
        #pragma unroll
        for (int r = 0; r < 4; ++r) {
            const int b = rg2 + r;
            xp2[r] = __ldg(&xh[b * HH + j2]);
            zv[r]  = Zb[b * HH + j2];
            hv2[r] = hstate[b * HH + j2];
        }
        CP_WAIT0();
        __syncthreads();

        float a2[4] = {0.f,0.f,0.f,0.f};
        #pragma unroll 1
        for (int i = 0; i < 16; ++i) {
            if (i < 15) {
                const int kn = (i + 1) * 64;
                #pragma unroll
                for (int u = 0; u < 4; ++u)
                    cp16(&ts[(i + 1) & 1][srow[u]][scol[u]],
                         &RH[srow[u] * HH + kn + scol[u]]);
                CP_COMMIT();
            }
            const float (*tb)[64] = ts[i & 1];
            #pragma unroll
            for (int k4 = 0; k4 < 16; ++k4) {
                const int q = i * 16 + k4;
                float4 wv = *(const float4*)&Wh24[q * 64 + lane2 * 4];
                #pragma unroll
                for (int r = 0; r < 4; ++r) {
                    float4 hv = *(const float4*)&tb[rg2 + r][4 * k4];
                    a2[r] = fmaf(hv.x, wv.x, a2[r]);
                    a2[r] = fmaf(hv.y, wv.y, a2[r]);
                    a2[r] = fmaf(hv.z, wv.z, a2[r]);
                    a2[r] = fmaf(hv.w, wv.w, a2[r]);
                }
            }
            if (i < 15) CP_WAIT0();
            __syncthreads();
        }
        #pragma unroll
        for (int r = 0; r < 4; ++r) {
            const int b = rg2 + r;
            float htil = tanhf(a2[r] + xp2[r]);
            float hnew = zv[r] * htil + (1.f - zv[r]) * hv2[r];
            hstate[b * HH + j2] = hnew;
            out[(size_t)(b * TT + t) * (2 * HH) + dir * HH + j2] = hnew;
        }
        dir_barrier(dir);
    }
}

// ---------------------------------------------------------------------------
extern "C" void kernel_launch(void* const* d_in, const int* in_sizes, int n_in,
                              void* d_out, int out_size) {
    (void)in_sizes; (void)n_in; (void)out_size;
    const float* x     = (const float*)d_in[0];
    const float* hf0   = (const float*)d_in[1];
    const float* hb0   = (const float*)d_in[2];
    const float* Whr_f = (const float*)d_in[3];
    const float* Wxr_f = (const float*)d_in[4];
    const float* br_f  = (const float*)d_in[5];
    const float* Whz_f = (const float*)d_in[6];
    const float* Wxz_f = (const float*)d_in[7];
    const float* bz_f  = (const float*)d_in[8];
    const float* Whh_f = (const float*)d_in[9];
    const float* Wxh_f = (const float*)d_in[10];
    const float* bh_f  = (const float*)d_in[11];
    const float* Whr_b = (const float*)d_in[12];
    const float* Wxr_b = (const float*)d_in[13];
    const float* br_b  = (const float*)d_in[14];
    const float* Whz_b = (const float*)d_in[15];
    const float* Wxz_b = (const float*)d_in[16];
    const float* bz_b  = (const float*)d_in[17];
    const float* Whh_b = (const float*)d_in[18];
    const float* Wxh_b = (const float*)d_in[19];
    const float* bh_b  = (const float*)d_in[20];
    float* out = (float*)d_out;

    static int smem_set = 0;
    if (!smem_set) {
        cudaFuncSetAttribute(gru_rec_kernel,
                             cudaFuncAttributeMaxDynamicSharedMemorySize,
                             SM_FLOATS * sizeof(float));
        smem_set = 1;
    }

    dim3 g1(TT * BB / 128, HH / 64, 6);
    inproj_kernel<<<g1, 256>>>(x,
        Wxr_f, br_f, Wxz_f, bz_f, Wxh_f, bh_f,
        Wxr_b, br_b, Wxz_b, bz_b, Wxh_b, bh_b);

    gru_rec_kernel<<<2 * NCTA_DIR, 256, SM_FLOATS * sizeof(float)>>>(hf0, hb0,
        Whr_f, Whz_f, Whh_f, Whr_b, Whz_b, Whh_b, out);
}

// round 7
// speedup vs baseline: 1.4962x; 1.4962x over previous
#include <cuda_runtime.h>

#define BB 64
#define TT 512
#define II 512
#define HH 1024
#define NCTA_DIR 64   // CTAs per direction; 128 total <= 148 SMs -> all co-resident

// ---------------- scratch (device globals; no allocations allowed) ----------
__device__ float g_Xrz[2][TT][BB][2 * HH]; // x@W_xr|x@W_xz (+bias), combined cols
__device__ float g_Xh [2][TT][BB][HH];     // x@W_xh (+bias)
__device__ float g_h  [2][BB][HH];         // current hidden state per direction
__device__ float g_RH [2][BB][HH];         // R * h   (phase1 -> phase2)
__device__ float g_Z  [2][BB][HH];         // Z gate  (phase1 -> phase2)
__device__ unsigned g_bar_count[2];
__device__ unsigned g_bar_gen[2];

// ------------- per-direction software grid barrier (generation-based) -------
__device__ __forceinline__ void dir_barrier(int dir) {
    __syncthreads();
    if (threadIdx.x == 0) {
        volatile unsigned* vgen = (volatile unsigned*)&g_bar_gen[dir];
        unsigned my = *vgen;
        __threadfence();
        unsigned a = atomicAdd(&g_bar_count[dir], 1u);
        if (a == NCTA_DIR - 1) {
            g_bar_count[dir] = 0;
            __threadfence();
            atomicAdd(&g_bar_gen[dir], 1u);
        } else {
            while (*vgen == my) { }
            __threadfence();
        }
    }
    __syncthreads();
}

// ---------------- input projection: 6x GEMM (32768x512)@(512x1024)+bias -----
// CTA: 256 threads -> 128x64 tile, 32 outputs/thread (8 rows x 4 cols)
__global__ void __launch_bounds__(256) inproj_kernel(
    const float* __restrict__ x,
    const float* __restrict__ Wr_f, const float* __restrict__ br_f,
    const float* __restrict__ Wz_f, const float* __restrict__ bz_f,
    const float* __restrict__ Wh_f, const float* __restrict__ bh_f,
    const float* __restrict__ Wr_b, const float* __restrict__ br_b,
    const float* __restrict__ Wz_b, const float* __restrict__ bz_b,
    const float* __restrict__ Wh_b, const float* __restrict__ bh_b)
{
    const int mat  = blockIdx.z;   // 0..5 : dir*3 + gate
    const int dir  = mat / 3;
    const int gate = mat % 3;      // 0=r, 1=z, 2=h
    const float* W; const float* bias;
    switch (mat) {
        case 0: W = Wr_f; bias = br_f; break;
        case 1: W = Wz_f; bias = bz_f; break;
        case 2: W = Wh_f; bias = bh_f; break;
        case 3: W = Wr_b; bias = br_b; break;
        case 4: W = Wz_b; bias = bz_b; break;
        default: W = Wh_b; bias = bh_b; break;
    }

    const int mTile = blockIdx.x;             // 256 row tiles of 128
    const int cTile = blockIdx.y;             // 16 col tiles of 64
    const int w     = threadIdx.x >> 5;       // warp 0..7
    const int lane  = threadIdx.x & 31;
    const int hf    = lane >> 4;              // half-warp
    const int rbase = w * 16 + hf * 8;        // 8 rows per thread
    const int jc    = cTile * 64 + (lane & 15) * 4;  // 4 cols per thread

    __shared__ float xs[128][64];
    float acc[8][4];
    #pragma unroll
    for (int r = 0; r < 8; ++r)
        #pragma unroll
        for (int c = 0; c < 4; ++c) acc[r][c] = 0.f;

    const float* xbase = x + (size_t)(mTile * 128) * II;

    #pragma unroll 1
    for (int kb = 0; kb < II; kb += 64) {
        // stage 128x64 x-tile
        #pragma unroll
        for (int u = 0; u < 8; ++u) {
            int e  = threadIdx.x + 256 * u;     // 0..2047
            int r  = e >> 4;
            int c4 = (e & 15) * 4;
            *(float4*)&xs[r][c4] = *(const float4*)(xbase + r * II + kb + c4);
        }
        __syncthreads();
        #pragma unroll
        for (int k4 = 0; k4 < 16; ++k4) {
            const int k = kb + 4 * k4;
            const float4 w0 = *(const float4*)&W[(k + 0) * HH + jc];
            const float4 w1 = *(const float4*)&W[(k + 1) * HH + jc];
            const float4 w2 = *(const float4*)&W[(k + 2) * HH + jc];
            const float4 w3 = *(const float4*)&W[(k + 3) * HH + jc];
            #pragma unroll
            for (int r = 0; r < 8; ++r) {
                float4 xv = *(const float4*)&xs[rbase + r][4 * k4];
                acc[r][0] = fmaf(xv.x, w0.x, acc[r][0]);
                acc[r][1] = fmaf(xv.x, w0.y, acc[r][1]);
                acc[r][2] = fmaf(xv.x, w0.z, acc[r][2]);
                acc[r][3] = fmaf(xv.x, w0.w, acc[r][3]);
                acc[r][0] = fmaf(xv.y, w1.x, acc[r][0]);
                acc[r][1] = fmaf(xv.y, w1.y, acc[r][1]);
                acc[r][2] = fmaf(xv.y, w1.z, acc[r][2]);
                acc[r][3] = fmaf(xv.y, w1.w, acc[r][3]);
                acc[r][0] = fmaf(xv.z, w2.x, acc[r][0]);
                acc[r][1] = fmaf(xv.z, w2.y, acc[r][1]);
                acc[r][2] = fmaf(xv.z, w2.z, acc[r][2]);
                acc[r][3] = fmaf(xv.z, w2.w, acc[r][3]);
                acc[r][0] = fmaf(xv.w, w3.x, acc[r][0]);
                acc[r][1] = fmaf(xv.w, w3.y, acc[r][1]);
                acc[r][2] = fmaf(xv.w, w3.z, acc[r][2]);
                acc[r][3] = fmaf(xv.w, w3.w, acc[r][3]);
            }
        }
        __syncthreads();
    }

    const float4 bv = *(const float4*)&bias[jc];
    #pragma unroll
    for (int r = 0; r < 8; ++r) {
        int row = mTile * 128 + rbase + r;   // row = b*T + t
        int b   = row >> 9;                  // /512
        int t   = row & (TT - 1);
        float4 v;
        v.x = acc[r][0] + bv.x;
        v.y = acc[r][1] + bv.y;
        v.z = acc[r][2] + bv.z;
        v.w = acc[r][3] + bv.w;
        if (gate == 0)      *(float4*)&g_Xrz[dir][t][b][jc]      = v;
        else if (gate == 1) *(float4*)&g_Xrz[dir][t][b][HH + jc] = v;
        else                *(float4*)&g_Xh [dir][t][b][jc]      = v;
    }
}

// ---------------- persistent bidirectional GRU recurrence -------------------
// 128 CTAs x 256 threads, 1 CTA/SM. Recurrent weights SMEM-resident (192KB);
// h/RH staging tiles double-buffered via REGISTER prefetch: the LDG for block
// i+1 issues at the top of block i's compute, the STS lands after it, and a
// single __syncthreads per block publishes the tile.
// Dynamic smem (floats):
//   Wrz4 [32768]   : phase1 weights [(k>>2)*128 + col*4 + (k&3)]
//   Wh24 [16384]   : phase2 weights [(k>>2)*64  + col*4 + (k&3)]
//   ts [2][64][64] : double-buffered staging tile
#define SM_WH2 32768
#define SM_TS  49152
#define SM_FLOATS (49152 + 2 * 64 * 64)

__global__ void __launch_bounds__(256) gru_rec_kernel(
    const float* __restrict__ hf0, const float* __restrict__ hb0,
    const float* __restrict__ Whr_f, const float* __restrict__ Whz_f, const float* __restrict__ Whh_f,
    const float* __restrict__ Whr_b, const float* __restrict__ Whz_b, const float* __restrict__ Whh_b,
    float* __restrict__ out)
{
    extern __shared__ float sm[];
    float* Wrz4 = sm;
    float* Wh24 = sm + SM_WH2;
    float (*ts)[64][64] = (float(*)[64][64])(sm + SM_TS);

    const int dir = blockIdx.x >> 6;
    const int c   = blockIdx.x & 63;

    const float* __restrict__ Whr = dir ? Whr_b : Whr_f;
    const float* __restrict__ Whz = dir ? Whz_b : Whz_f;
    const float* __restrict__ Whh = dir ? Whh_b : Whh_f;
    const float* __restrict__ h0  = dir ? hb0   : hf0;

    float* __restrict__ hstate = &g_h [dir][0][0];
    float* __restrict__ RH     = &g_RH[dir][0][0];
    float* __restrict__ Zb     = &g_Z [dir][0][0];

    // phase1 geometry: 32 combined cols/CTA over 2048; 8 rows/thread
    const int lane1 = threadIdx.x & 31;
    const int rg1   = (threadIdx.x >> 5) * 8;
    const int jj    = c * 32 + lane1;            // 0..2047 combined [R|Z]
    const float* __restrict__ Wg = (jj < HH) ? Whr : Whz;
    const int jw    = jj & (HH - 1);

    // phase2 geometry: 16 cols/CTA over 1024; 4 rows/thread
    const int lane2 = threadIdx.x & 15;
    const int rg2   = (threadIdx.x >> 4) * 4;
    const int j2    = c * 16 + lane2;

    // staging geometry: four float4 per thread per kb (full 64x64 tile)
    int srow[4], scol[4];
    #pragma unroll
    for (int u = 0; u < 4; ++u) {
        int e = threadIdx.x + 256 * u;   // 0..1023
        srow[u] = e >> 4;                // 0..63
        scol[u] = (e & 15) * 4;          // 0..60
    }

    // ---- one-time: cache this CTA's weight columns into SMEM ----
    {
        const int wp = threadIdx.x >> 5;
        for (int k = wp; k < HH; k += 8)                 // phase1: col = jj
            Wrz4[(k >> 2) * 128 + lane1 * 4 + (k & 3)] = Wg[k * HH + jw];
        const int wp2 = threadIdx.x >> 4;
        for (int k = wp2; k < HH; k += 16)               // phase2: col = j2
            Wh24[(k >> 2) * 64 + lane2 * 4 + (k & 3)] = Whh[k * HH + j2];
    }

    // init hidden state from h_prev (re-done every replay: deterministic)
    {
        int base = c * 1024;
        #pragma unroll
        for (int u = 0; u < 4; ++u)
            hstate[base + u * 256 + threadIdx.x] = h0[base + u * 256 + threadIdx.x];
    }
    dir_barrier(dir);

    for (int step = 0; step < TT; ++step) {
        const int t = dir ? (TT - 1 - step) : step;

        // ------------------ phase 1: [R|Z] = sigmoid(h@W + x) -------------
        const float* __restrict__ xrz = &g_Xrz[dir][t][0][0];

        // stage kb=0 synchronously
        #pragma unroll
        for (int u = 0; u < 4; ++u)
            *(float4*)&ts[0][srow[u]][scol[u]] =
                *(const float4*)&hstate[srow[u] * HH + scol[u]];

        float xpre[8], hold1[8];
        #pragma unroll
        for (int r = 0; r < 8; ++r) {              // prefetch epilogue operands
            xpre[r]  = __ldg(&xrz[(rg1 + r) * (2 * HH) + jj]);
            hold1[r] = hstate[(rg1 + r) * HH + jw];
        }
        __syncthreads();

        float acc[8] = {0.f,0.f,0.f,0.f,0.f,0.f,0.f,0.f};
        #pragma unroll 1
        for (int i = 0; i < 16; ++i) {
            float4 pf[4];
            if (i < 15) {
                const int kn = (i + 1) * 64;
                #pragma unroll
                for (int u = 0; u < 4; ++u)
                    pf[u] = *(const float4*)&hstate[srow[u] * HH + kn + scol[u]];
            }
            const float (*tb)[64] = ts[i & 1];
            #pragma unroll
            for (int k4 = 0; k4 < 16; ++k4) {
                const int q = i * 16 + k4;
                float4 wv = *(const float4*)&Wrz4[q * 128 + lane1 * 4];
                #pragma unroll
                for (int r = 0; r < 8; ++r) {
                    float4 hv = *(const float4*)&tb[rg1 + r][4 * k4];
                    acc[r] = fmaf(hv.x, wv.x, acc[r]);
                    acc[r] = fmaf(hv.y, wv.y, acc[r]);
                    acc[r] = fmaf(hv.z, wv.z, acc[r]);
                    acc[r] = fmaf(hv.w, wv.w, acc[r]);
                }
            }
            if (i < 15) {
                #pragma unroll
                for (int u = 0; u < 4; ++u)
                    *(float4*)&ts[(i + 1) & 1][srow[u]][scol[u]] = pf[u];
                __syncthreads();
            }
        }
        #pragma unroll
        for (int r = 0; r < 8; ++r) {
            const int b = rg1 + r;
            float pre = acc[r] + xpre[r];
            float s   = 1.f / (1.f + __expf(-pre));
            if (jj < HH) RH[b * HH + jw] = s * hold1[r];
            else         Zb[b * HH + jw] = s;
        }
        dir_barrier(dir);

        // ------------------ phase 2: h = Z*tanh(RH@Whh + xh) + (1-Z)*h ----
        const float* __restrict__ xh = &g_Xh[dir][t][0][0];

        #pragma unroll
        for (int u = 0; u < 4; ++u)
            *(float4*)&ts[0][srow[u]][scol[u]] =
                *(const float4*)&RH[srow[u] * HH + scol[u]];

        float xp2[4], zv[4], hv2[4];
        #pragma unroll
        for (int r = 0; r < 4; ++r) {
            const int b = rg2 + r;
            xp2[r] = __ldg(&xh[b * HH + j2]);
            zv[r]  = Zb[b * HH + j2];
            hv2[r] = hstate[b * HH + j2];
        }
        __syncthreads();

        float a2[4] = {0.f,0.f,0.f,0.f};
        #pragma unroll 1
        for (int i = 0; i < 16; ++i) {
            float4 pf[4];
            if (i < 15) {
                const int kn = (i + 1) * 64;
                #pragma unroll
                for (int u = 0; u < 4; ++u)
                    pf[u] = *(const float4*)&RH[srow[u] * HH + kn + scol[u]];
            }
            const float (*tb)[64] = ts[i & 1];
            #pragma unroll
            for (int k4 = 0; k4 < 16; ++k4) {
                const int q = i * 16 + k4;
                float4 wv = *(const float4*)&Wh24[q * 64 + lane2 * 4];
                #pragma unroll
                for (int r = 0; r < 4; ++r) {
                    float4 hv = *(const float4*)&tb[rg2 + r][4 * k4];
                    a2[r] = fmaf(hv.x, wv.x, a2[r]);
                    a2[r] = fmaf(hv.y, wv.y, a2[r]);
                    a2[r] = fmaf(hv.z, wv.z, a2[r]);
                    a2[r] = fmaf(hv.w, wv.w, a2[r]);
                }
            }
            if (i < 15) {
                #pragma unroll
                for (int u = 0; u < 4; ++u)
                    *(float4*)&ts[(i + 1) & 1][srow[u]][scol[u]] = pf[u];
                __syncthreads();
            }
        }
        #pragma unroll
        for (int r = 0; r < 4; ++r) {
            const int b = rg2 + r;
            float htil = tanhf(a2[r] + xp2[r]);
            float hnew = zv[r] * htil + (1.f - zv[r]) * hv2[r];
            hstate[b * HH + j2] = hnew;
            out[(size_t)(b * TT + t) * (2 * HH) + dir * HH + j2] = hnew;
        }
        dir_barrier(dir);
    }
}

// ---------------------------------------------------------------------------
extern "C" void kernel_launch(void* const* d_in, const int* in_sizes, int n_in,
                              void* d_out, int out_size) {
    (void)in_sizes; (void)n_in; (void)out_size;
    const float* x     = (const float*)d_in[0];
    const float* hf0   = (const float*)d_in[1];
    const float* hb0   = (const float*)d_in[2];
    const float* Whr_f = (const float*)d_in[3];
    const float* Wxr_f = (const float*)d_in[4];
    const float* br_f  = (const float*)d_in[5];
    const float* Whz_f = (const float*)d_in[6];
    const float* Wxz_f = (const float*)d_in[7];
    const float* bz_f  = (const float*)d_in[8];
    const float* Whh_f = (const float*)d_in[9];
    const float* Wxh_f = (const float*)d_in[10];
    const float* bh_f  = (const float*)d_in[11];
    const float* Whr_b = (const float*)d_in[12];
    const float* Wxr_b = (const float*)d_in[13];
    const float* br_b  = (const float*)d_in[14];
    const float* Whz_b = (const float*)d_in[15];
    const float* Wxz_b = (const float*)d_in[16];
    const float* bz_b  = (const float*)d_in[17];
    const float* Whh_b = (const float*)d_in[18];
    const float* Wxh_b = (const float*)d_in[19];
    const float* bh_b  = (const float*)d_in[20];
    float* out = (float*)d_out;

    static int smem_set = 0;
    if (!smem_set) {
        cudaFuncSetAttribute(gru_rec_kernel,
                             cudaFuncAttributeMaxDynamicSharedMemorySize,
                             SM_FLOATS * sizeof(float));
        smem_set = 1;
    }

    dim3 g1(TT * BB / 128, HH / 64, 6);
    inproj_kernel<<<g1, 256>>>(x,
        Wxr_f, br_f, Wxz_f, bz_f, Wxh_f, bh_f,
        Wxr_b, br_b, Wxz_b, bz_b, Wxh_b, bh_b);

    gru_rec_kernel<<<2 * NCTA_DIR, 256, SM_FLOATS * sizeof(float)>>>(hf0, hb0,
        Whr_f, Whz_f, Whh_f, Whr_b, Whz_b, Whh_b, out);
}

// round 8
// speedup vs baseline: 1.6680x; 1.1148x over previous
#include <cuda_runtime.h>

#define BB 64
#define TT 512
#define II 512
#define HH 1024
#define NCTA_DIR 64   // CTAs per direction; 128 total <= 148 SMs -> all co-resident

// ---------------- scratch (device globals; no allocations allowed) ----------
__device__ float g_Xrz[2][TT][BB][2 * HH]; // x@W_xr|x@W_xz (+bias), combined cols
__device__ float g_Xh [2][TT][BB][HH];     // x@W_xh (+bias)
__device__ float g_h  [2][BB][HH];         // current hidden state per direction
__device__ float g_RH [2][BB][HH];         // R * h   (phase1 -> phase2)
__device__ float g_Z  [2][BB][HH];         // Z gate  (phase1 -> phase2)
__device__ unsigned g_bar_count[2];
__device__ unsigned g_bar_gen[2];

#define HBAR(id) asm volatile("bar.sync %0, 256;" :: "r"(id) : "memory")

// ------------- per-direction software grid barrier (generation-based) -------
__device__ __forceinline__ void dir_barrier(int dir) {
    __syncthreads();
    if (threadIdx.x == 0) {
        volatile unsigned* vgen = (volatile unsigned*)&g_bar_gen[dir];
        unsigned my = *vgen;
        __threadfence();
        unsigned a = atomicAdd(&g_bar_count[dir], 1u);
        if (a == NCTA_DIR - 1) {
            g_bar_count[dir] = 0;
            __threadfence();
            atomicAdd(&g_bar_gen[dir], 1u);
        } else {
            while (*vgen == my) { }
            __threadfence();
        }
    }
    __syncthreads();
}

// ---------------- input projection: 6x GEMM (32768x512)@(512x1024)+bias -----
// CTA: 256 threads -> 128x64 tile, 32 outputs/thread (8 rows x 4 cols)
__global__ void __launch_bounds__(256) inproj_kernel(
    const float* __restrict__ x,
    const float* __restrict__ Wr_f, const float* __restrict__ br_f,
    const float* __restrict__ Wz_f, const float* __restrict__ bz_f,
    const float* __restrict__ Wh_f, const float* __restrict__ bh_f,
    const float* __restrict__ Wr_b, const float* __restrict__ br_b,
    const float* __restrict__ Wz_b, const float* __restrict__ bz_b,
    const float* __restrict__ Wh_b, const float* __restrict__ bh_b)
{
    const int mat  = blockIdx.z;   // 0..5 : dir*3 + gate
    const int dir  = mat / 3;
    const int gate = mat % 3;      // 0=r, 1=z, 2=h
    const float* W; const float* bias;
    switch (mat) {
        case 0: W = Wr_f; bias = br_f; break;
        case 1: W = Wz_f; bias = bz_f; break;
        case 2: W = Wh_f; bias = bh_f; break;
        case 3: W = Wr_b; bias = br_b; break;
        case 4: W = Wz_b; bias = bz_b; break;
        default: W = Wh_b; bias = bh_b; break;
    }

    const int mTile = blockIdx.x;             // 256 row tiles of 128
    const int cTile = blockIdx.y;             // 16 col tiles of 64
    const int w     = threadIdx.x >> 5;       // warp 0..7
    const int lane  = threadIdx.x & 31;
    const int hf    = lane >> 4;              // half-warp
    const int rbase = w * 16 + hf * 8;        // 8 rows per thread
    const int jc    = cTile * 64 + (lane & 15) * 4;  // 4 cols per thread

    __shared__ float xs[128][64];
    float acc[8][4];
    #pragma unroll
    for (int r = 0; r < 8; ++r)
        #pragma unroll
        for (int c = 0; c < 4; ++c) acc[r][c] = 0.f;

    const float* xbase = x + (size_t)(mTile * 128) * II;

    #pragma unroll 1
    for (int kb = 0; kb < II; kb += 64) {
        // stage 128x64 x-tile
        #pragma unroll
        for (int u = 0; u < 8; ++u) {
            int e  = threadIdx.x + 256 * u;     // 0..2047
            int r  = e >> 4;
            int c4 = (e & 15) * 4;
            *(float4*)&xs[r][c4] = *(const float4*)(xbase + r * II + kb + c4);
        }
        __syncthreads();
        #pragma unroll
        for (int k4 = 0; k4 < 16; ++k4) {
            const int k = kb + 4 * k4;
            const float4 w0 = *(const float4*)&W[(k + 0) * HH + jc];
            const float4 w1 = *(const float4*)&W[(k + 1) * HH + jc];
            const float4 w2 = *(const float4*)&W[(k + 2) * HH + jc];
            const float4 w3 = *(const float4*)&W[(k + 3) * HH + jc];
            #pragma unroll
            for (int r = 0; r < 8; ++r) {
                float4 xv = *(const float4*)&xs[rbase + r][4 * k4];
                acc[r][0] = fmaf(xv.x, w0.x, acc[r][0]);
                acc[r][1] = fmaf(xv.x, w0.y, acc[r][1]);
                acc[r][2] = fmaf(xv.x, w0.z, acc[r][2]);
                acc[r][3] = fmaf(xv.x, w0.w, acc[r][3]);
                acc[r][0] = fmaf(xv.y, w1.x, acc[r][0]);
                acc[r][1] = fmaf(xv.y, w1.y, acc[r][1]);
                acc[r][2] = fmaf(xv.y, w1.z, acc[r][2]);
                acc[r][3] = fmaf(xv.y, w1.w, acc[r][3]);
                acc[r][0] = fmaf(xv.z, w2.x, acc[r][0]);
                acc[r][1] = fmaf(xv.z, w2.y, acc[r][1]);
                acc[r][2] = fmaf(xv.z, w2.z, acc[r][2]);
                acc[r][3] = fmaf(xv.z, w2.w, acc[r][3]);
                acc[r][0] = fmaf(xv.w, w3.x, acc[r][0]);
                acc[r][1] = fmaf(xv.w, w3.y, acc[r][1]);
                acc[r][2] = fmaf(xv.w, w3.z, acc[r][2]);
                acc[r][3] = fmaf(xv.w, w3.w, acc[r][3]);
            }
        }
        __syncthreads();
    }

    const float4 bv = *(const float4*)&bias[jc];
    #pragma unroll
    for (int r = 0; r < 8; ++r) {
        int row = mTile * 128 + rbase + r;   // row = b*T + t
        int b   = row >> 9;                  // /512
        int t   = row & (TT - 1);
        float4 v;
        v.x = acc[r][0] + bv.x;
        v.y = acc[r][1] + bv.y;
        v.z = acc[r][2] + bv.z;
        v.w = acc[r][3] + bv.w;
        if (gate == 0)      *(float4*)&g_Xrz[dir][t][b][jc]      = v;
        else if (gate == 1) *(float4*)&g_Xrz[dir][t][b][HH + jc] = v;
        else                *(float4*)&g_Xh [dir][t][b][jc]      = v;
    }
}

// ---------------- persistent bidirectional GRU recurrence -------------------
// 128 CTAs x 512 threads, 1 CTA/SM. K-SPLIT: threads [0,256) compute k in
// [0,512), threads [256,512) compute k in [512,1024) with the IDENTICAL
// per-thread microkernel. Each half stages its own 64x64 tile in its own
// buffer and syncs with half-CTA named barriers, so 4 warps/SMSP interleave.
// Upper half deposits partial sums in its (then idle) tile buffer; lower
// half adds them and runs the epilogue.
// Dynamic smem (floats):
//   Wrz4 [32768]    : phase1 weights [(k>>2)*128 + col*4 + (k&3)]
//   Wh24 [16384]    : phase2 weights [(k>>2)*64  + col*4 + (k&3)]
//   ts [2][64][64]  : per-half staging tile (ts[1] doubles as psum buffer)
#define SM_WH2 32768
#define SM_TS  49152
#define SM_FLOATS (49152 + 2 * 64 * 64)

__global__ void __launch_bounds__(512) gru_rec_kernel(
    const float* __restrict__ hf0, const float* __restrict__ hb0,
    const float* __restrict__ Whr_f, const float* __restrict__ Whz_f, const float* __restrict__ Whh_f,
    const float* __restrict__ Whr_b, const float* __restrict__ Whz_b, const float* __restrict__ Whh_b,
    float* __restrict__ out)
{
    extern __shared__ float sm[];
    float* Wrz4 = sm;
    float* Wh24 = sm + SM_WH2;
    float (*ts)[64][64] = (float(*)[64][64])(sm + SM_TS);

    const int tid  = threadIdx.x;
    const int half = tid >> 8;          // 0: k in [0,512)   1: k in [512,1024)
    const int tidh = tid & 255;
    const int barid = 1 + half;
    const int koff  = half * 512;

    const int dir = blockIdx.x >> 6;
    const int c   = blockIdx.x & 63;

    const float* __restrict__ Whr = dir ? Whr_b : Whr_f;
    const float* __restrict__ Whz = dir ? Whz_b : Whz_f;
    const float* __restrict__ Whh = dir ? Whh_b : Whh_f;
    const float* __restrict__ h0  = dir ? hb0   : hf0;

    float* __restrict__ hstate = &g_h [dir][0][0];
    float* __restrict__ RH     = &g_RH[dir][0][0];
    float* __restrict__ Zb     = &g_Z [dir][0][0];
    float* __restrict__ psum   = &ts[1][0][0];   // upper tile doubles as psum

    // phase1 geometry (per half): 32 combined cols/CTA; 8 rows/thread
    const int lane1 = tidh & 31;
    const int rg1   = (tidh >> 5) * 8;
    const int jj    = c * 32 + lane1;            // 0..2047 combined [R|Z]
    const float* __restrict__ Wg = (jj < HH) ? Whr : Whz;
    const int jw    = jj & (HH - 1);

    // phase2 geometry (per half): 16 cols/CTA; 4 rows/thread
    const int lane2 = tidh & 15;
    const int rg2   = (tidh >> 4) * 4;
    const int j2    = c * 16 + lane2;

    // staging geometry: four float4 per thread per block (full 64x64 tile)
    int srow[4], scol[4];
    #pragma unroll
    for (int u = 0; u < 4; ++u) {
        int e = tidh + 256 * u;
        srow[u] = e >> 4;
        scol[u] = (e & 15) * 4;
    }

    // ---- one-time: cache this CTA's weight columns into SMEM (512 thr) ----
    {
        const int l1 = tid & 31;
        const int jwl = (c * 32 + l1) & (HH - 1);
        const float* __restrict__ Wgl = ((c * 32 + l1) < HH) ? Whr : Whz;
        for (int k = tid >> 5; k < HH; k += 16)
            Wrz4[(k >> 2) * 128 + l1 * 4 + (k & 3)] = Wgl[k * HH + jwl];
        const int l2 = tid & 15;
        const int j2l = c * 16 + l2;
        for (int k = tid >> 4; k < HH; k += 32)
            Wh24[(k >> 2) * 64 + l2 * 4 + (k & 3)] = Whh[k * HH + j2l];
    }
    // init hidden state (re-done every replay: deterministic)
    {
        int base = c * 1024;
        hstate[base + tid]       = h0[base + tid];
        hstate[base + 512 + tid] = h0[base + 512 + tid];
    }
    dir_barrier(dir);

    for (int step = 0; step < TT; ++step) {
        const int t = dir ? (TT - 1 - step) : step;

        // ------------------ phase 1: [R|Z] = sigmoid(h@W + x) -------------
        const float* __restrict__ xrz = &g_Xrz[dir][t][0][0];

        float xpre[8], hold1[8];
        if (half == 0) {
            #pragma unroll
            for (int r = 0; r < 8; ++r) {          // epilogue operand prefetch
                xpre[r]  = __ldg(&xrz[(rg1 + r) * (2 * HH) + jj]);
                hold1[r] = hstate[(rg1 + r) * HH + jw];
            }
        }

        // stage block 0 of this half
        #pragma unroll
        for (int u = 0; u < 4; ++u)
            *(float4*)&ts[half][srow[u]][scol[u]] =
                *(const float4*)&hstate[srow[u] * HH + koff + scol[u]];
        HBAR(barid);

        float acc[8] = {0.f,0.f,0.f,0.f,0.f,0.f,0.f,0.f};
        #pragma unroll 1
        for (int i = 0; i < 8; ++i) {
            float4 pf[4];
            if (i < 7) {
                const int kn = koff + (i + 1) * 64;
                #pragma unroll
                for (int u = 0; u < 4; ++u)
                    pf[u] = *(const float4*)&hstate[srow[u] * HH + kn + scol[u]];
            }
            #pragma unroll
            for (int k4 = 0; k4 < 16; ++k4) {
                const int q = half * 128 + i * 16 + k4;
                float4 wv = *(const float4*)&Wrz4[q * 128 + lane1 * 4];
                #pragma unroll
                for (int r = 0; r < 8; ++r) {
                    float4 hv = *(const float4*)&ts[half][rg1 + r][4 * k4];
                    acc[r] = fmaf(hv.x, wv.x, acc[r]);
                    acc[r] = fmaf(hv.y, wv.y, acc[r]);
                    acc[r] = fmaf(hv.z, wv.z, acc[r]);
                    acc[r] = fmaf(hv.w, wv.w, acc[r]);
                }
            }
            HBAR(barid);
            if (i < 7) {
                #pragma unroll
                for (int u = 0; u < 4; ++u)
                    *(float4*)&ts[half][srow[u]][scol[u]] = pf[u];
                HBAR(barid);
            }
        }
        // upper half deposits partials into its (now idle) tile buffer
        if (half == 1) {
            #pragma unroll
            for (int r = 0; r < 8; ++r)
                psum[(rg1 + r) * 32 + lane1] = acc[r];
        }
        __syncthreads();
        if (half == 0) {
            #pragma unroll
            for (int r = 0; r < 8; ++r) {
                const int b = rg1 + r;
                float pre = acc[r] + psum[b * 32 + lane1] + xpre[r];
                float s   = 1.f / (1.f + __expf(-pre));
                if (jj < HH) RH[b * HH + jw] = s * hold1[r];
                else         Zb[b * HH + jw] = s;
            }
        }
        dir_barrier(dir);

        // ------------------ phase 2: h = Z*tanh(RH@Whh + xh) + (1-Z)*h ----
        const float* __restrict__ xh = &g_Xh[dir][t][0][0];

        float xp2[4], zv[4], hv2[4];
        if (half == 0) {
            #pragma unroll
            for (int r = 0; r < 4; ++r) {
                const int b = rg2 + r;
                xp2[r] = __ldg(&xh[b * HH + j2]);
                zv[r]  = Zb[b * HH + j2];
                hv2[r] = hstate[b * HH + j2];
            }
        }

        #pragma unroll
        for (int u = 0; u < 4; ++u)
            *(float4*)&ts[half][srow[u]][scol[u]] =
                *(const float4*)&RH[srow[u] * HH + koff + scol[u]];
        HBAR(barid);

        float a2[4] = {0.f,0.f,0.f,0.f};
        #pragma unroll 1
        for (int i = 0; i < 8; ++i) {
            float4 pf[4];
            if (i < 7) {
                const int kn = koff + (i + 1) * 64;
                #pragma unroll
                for (int u = 0; u < 4; ++u)
                    pf[u] = *(const float4*)&RH[srow[u] * HH + kn + scol[u]];
            }
            #pragma unroll
            for (int k4 = 0; k4 < 16; ++k4) {
                const int q = half * 128 + i * 16 + k4;
                float4 wv = *(const float4*)&Wh24[q * 64 + lane2 * 4];
                #pragma unroll
                for (int r = 0; r < 4; ++r) {
                    float4 hv = *(const float4*)&ts[half][rg2 + r][4 * k4];
                    a2[r] = fmaf(hv.x, wv.x, a2[r]);
                    a2[r] = fmaf(hv.y, wv.y, a2[r]);
                    a2[r] = fmaf(hv.z, wv.z, a2[r]);
                    a2[r] = fmaf(hv.w, wv.w, a2[r]);
                }
            }
            HBAR(barid);
            if (i < 7) {
                #pragma unroll
                for (int u = 0; u < 4; ++u)
                    *(float4*)&ts[half][srow[u]][scol[u]] = pf[u];
                HBAR(barid);
            }
        }
        if (half == 1) {
            #pragma unroll
            for (int r = 0; r < 4; ++r)
                psum[(rg2 + r) * 16 + lane2] = a2[r];
        }
        __syncthreads();
        if (half == 0) {
            #pragma unroll
            for (int r = 0; r < 4; ++r) {
                const int b = rg2 + r;
                float htil = tanhf(a2[r] + psum[b * 16 + lane2] + xp2[r]);
                float hnew = zv[r] * htil + (1.f - zv[r]) * hv2[r];
                hstate[b * HH + j2] = hnew;
                out[(size_t)(b * TT + t) * (2 * HH) + dir * HH + j2] = hnew;
            }
        }
        dir_barrier(dir);
    }
}

// ---------------------------------------------------------------------------
extern "C" void kernel_launch(void* const* d_in, const int* in_sizes, int n_in,
                              void* d_out, int out_size) {
    (void)in_sizes; (void)n_in; (void)out_size;
    const float* x     = (const float*)d_in[0];
    const float* hf0   = (const float*)d_in[1];
    const float* hb0   = (const float*)d_in[2];
    const float* Whr_f = (const float*)d_in[3];
    const float* Wxr_f = (const float*)d_in[4];
    const float* br_f  = (const float*)d_in[5];
    const float* Whz_f = (const float*)d_in[6];
    const float* Wxz_f = (const float*)d_in[7];
    const float* bz_f  = (const float*)d_in[8];
    const float* Whh_f = (const float*)d_in[9];
    const float* Wxh_f = (const float*)d_in[10];
    const float* bh_f  = (const float*)d_in[11];
    const float* Whr_b = (const float*)d_in[12];
    const float* Wxr_b = (const float*)d_in[13];
    const float* br_b  = (const float*)d_in[14];
    const float* Whz_b = (const float*)d_in[15];
    const float* Wxz_b = (const float*)d_in[16];
    const float* bz_b  = (const float*)d_in[17];
    const float* Whh_b = (const float*)d_in[18];
    const float* Wxh_b = (const float*)d_in[19];
    const float* bh_b  = (const float*)d_in[20];
    float* out = (float*)d_out;

    static int smem_set = 0;
    if (!smem_set) {
        cudaFuncSetAttribute(gru_rec_kernel,
                             cudaFuncAttributeMaxDynamicSharedMemorySize,
                             SM_FLOATS * sizeof(float));
        smem_set = 1;
    }

    dim3 g1(TT * BB / 128, HH / 64, 6);
    inproj_kernel<<<g1, 256>>>(x,
        Wxr_f, br_f, Wxz_f, bz_f, Wxh_f, bh_f,
        Wxr_b, br_b, Wxz_b, bz_b, Wxh_b, bh_b);

    gru_rec_kernel<<<2 * NCTA_DIR, 512, SM_FLOATS * sizeof(float)>>>(hf0, hb0,
        Whr_f, Whz_f, Whh_f, Whr_b, Whz_b, Whh_b, out);
}